// round 5
// baseline (speedup 1.0000x reference)
#include <cuda_runtime.h>
#include <cuda_bf16.h>
#include <cstdint>

// ============================================================================
// NT-Xent loss, GB300 (sm_103a) -- single fused persistent kernel:
//   phase 0: normalize rows -> bf16 (high-MLP)
//   [grid barrier]
//   phase 1: symmetric Gram HMMA + fused exp-sum epilogue (cp.async dbl-buf B)
//   [grid barrier]
//   phase 2: finalize -> scalar loss; last CTA resets barrier state
// 296 CTAs = exactly 2/SM (launch_bounds(256,2), 96KB smem) -> co-resident,
// so software grid barriers are safe.
// ============================================================================

#define N_TOTAL 8192
#define HALF    4096
#define DIM     128
#define TWO_LOG2E 2.8853900817779268f
#define LOG2E     1.4426950408889634f

#define GRID_GRAM 296

__device__ __nv_bfloat16 g_znb[N_TOTAL * DIM];
__device__ float g_rowsum[N_TOTAL];
__device__ float g_pos[N_TOTAL];
__device__ float g_exc[N_TOTAL];
__device__ float g_acc;
__device__ unsigned int g_cnt;
__device__ unsigned int g_bar0, g_rel0, g_bar1, g_rel1;

__device__ __forceinline__ uint32_t smem_to_u32(const void* p) {
    uint32_t a;
    asm("{ .reg .u64 t; cvta.to.shared.u64 t, %1; cvt.u32.u64 %0, t; }"
        : "=r"(a) : "l"(p));
    return a;
}
__device__ __forceinline__ float ex2_approx(float x) {
    float y;
    asm("ex2.approx.f32 %0, %1;" : "=f"(y) : "f"(x));
    return y;
}

__device__ __forceinline__ void grid_barrier(unsigned int* bar, unsigned int* rel) {
    __syncthreads();
    if (threadIdx.x == 0) {
        __threadfence();
        unsigned a = atomicAdd(bar, 1u);
        if (a == GRID_GRAM - 1) {
            __threadfence();
            *(volatile unsigned int*)rel = 1u;
        } else {
            while (*(volatile unsigned int*)rel == 0u) { }
        }
        __threadfence();
    }
    __syncthreads();
}

// ============================================================================
// smem: A 32KB | B0 32KB | B1 32KB
// ============================================================================
#define SMEM_A   0
#define SMEM_B0  32768
#define SMEM_TOT 98304

__device__ __forceinline__ uint32_t tile_off(int row, int chunk16) {
    return (uint32_t)(row * 256 + ((chunk16 ^ (row & 7)) << 4));
}

__device__ __forceinline__ void load_tile_async(uint32_t sdst, int row0, int tid) {
    const uint4* gp = reinterpret_cast<const uint4*>(g_znb + (size_t)row0 * DIM);
    #pragma unroll
    for (int it = 0; it < 8; it++) {
        int idx = tid + it * 256;
        int row = idx >> 4, ch = idx & 15;
        asm volatile("cp.async.cg.shared.global [%0], [%1], 16;"
            :: "r"(sdst + tile_off(row, ch)), "l"(gp + (row << 4) + ch));
    }
}
#define CP_COMMIT() asm volatile("cp.async.commit_group;" ::: "memory")
#define CP_WAIT0()  asm volatile("cp.async.wait_group 0;"  ::: "memory")

__global__ void __launch_bounds__(256, 2)
fused_kernel(const float* __restrict__ zi, const float* __restrict__ zj,
             float* __restrict__ out) {
    extern __shared__ char smem[];
    uint32_t sb = smem_to_u32(smem);
    const int tid  = threadIdx.x;
    const int wid  = tid >> 5;
    const int lane = tid & 31;
    const int bid  = blockIdx.x;

    // ======================= phase 0: normalize ============================
    {
        const int gw = bid * 8 + wid;           // 0..2367 global warp id
        #pragma unroll
        for (int row = gw; row < N_TOTAL; row += GRID_GRAM * 8) {
            const float* src = (row < HALF) ? (zi + (size_t)row * DIM)
                                            : (zj + (size_t)(row - HALF) * DIM);
            float4 v = reinterpret_cast<const float4*>(src)[lane];
            float ss = v.x * v.x + v.y * v.y + v.z * v.z + v.w * v.w;
            #pragma unroll
            for (int o = 16; o; o >>= 1) ss += __shfl_xor_sync(0xFFFFFFFFu, ss, o);
            float inv = 1.0f / fmaxf(sqrtf(ss), 1e-8f);
            __nv_bfloat162* dst =
                reinterpret_cast<__nv_bfloat162*>(g_znb + (size_t)row * DIM + lane * 4);
            dst[0] = __floats2bfloat162_rn(v.x * inv, v.y * inv);
            dst[1] = __floats2bfloat162_rn(v.z * inv, v.w * inv);
            if (lane == 0) g_rowsum[row] = 0.0f;
        }
    }
    grid_barrier(&g_bar0, &g_rel0);

    // ======================= phase 1: symmetric Gram =======================
    {
        const int start = bid * 7 + (bid < 8 ? bid : 8);
        const int count = (bid < 8) ? 8 : 7;

        int mi = 0, rem = start, len = 64;
        while (rem >= len) { rem -= len; len--; mi++; }
        int ni = mi + rem;

        const int wm = (wid & 3) * 32;
        const int wn = (wid >> 2) * 64;
        const int l7 = lane & 7;
        const int g  = lane >> 3;

        load_tile_async(sb + SMEM_A, mi << 7, tid);
        load_tile_async(sb + SMEM_B0, ni << 7, tid);
        CP_COMMIT();
        CP_WAIT0();
        __syncthreads();
        int cur = 0;

        for (int i = 0; i < count; i++) {
            const int m0 = mi << 7, n0 = ni << 7;
            const bool diag = (mi == ni);
            const bool last = (i == count - 1);
            int mi_n = mi, ni_n = ni + 1;
            if (ni_n == 64) { mi_n = mi + 1; ni_n = mi_n; }
            const bool pf = !last && (mi_n == mi);
            if (pf) {
                load_tile_async(sb + SMEM_B0 + ((1 - cur) << 15), ni_n << 7, tid);
                CP_COMMIT();
            }
            const uint32_t bbase = sb + SMEM_B0 + (cur << 15);

            float c[2][8][4];
            #pragma unroll
            for (int mt = 0; mt < 2; mt++)
                #pragma unroll
                for (int nt = 0; nt < 8; nt++)
                    #pragma unroll
                    for (int q = 0; q < 4; q++) c[mt][nt][q] = 0.0f;

            #pragma unroll
            for (int ks = 0; ks < 8; ks++) {
                uint32_t a[2][4];
                #pragma unroll
                for (int mt = 0; mt < 2; mt++) {
                    int row = wm + mt * 16 + l7 + ((g & 1) << 3);
                    int ch  = ks * 2 + (g >> 1);
                    uint32_t addr = sb + SMEM_A + tile_off(row, ch);
                    asm volatile(
                        "ldmatrix.sync.aligned.m8n8.x4.shared.b16 {%0,%1,%2,%3}, [%4];"
                        : "=r"(a[mt][0]), "=r"(a[mt][1]), "=r"(a[mt][2]), "=r"(a[mt][3])
                        : "r"(addr));
                }
                uint32_t b[8][2];
                #pragma unroll
                for (int nt2 = 0; nt2 < 4; nt2++) {
                    int row = wn + nt2 * 16 + l7 + ((g >> 1) << 3);
                    int ch  = ks * 2 + (g & 1);
                    uint32_t addr = bbase + tile_off(row, ch);
                    asm volatile(
                        "ldmatrix.sync.aligned.m8n8.x4.shared.b16 {%0,%1,%2,%3}, [%4];"
                        : "=r"(b[nt2 * 2][0]),     "=r"(b[nt2 * 2][1]),
                          "=r"(b[nt2 * 2 + 1][0]), "=r"(b[nt2 * 2 + 1][1])
                        : "r"(addr));
                }
                #pragma unroll
                for (int mt = 0; mt < 2; mt++)
                    #pragma unroll
                    for (int nt = 0; nt < 8; nt++)
                        asm volatile(
                            "mma.sync.aligned.m16n8k16.row.col.f32.bf16.bf16.f32 "
                            "{%0,%1,%2,%3}, {%4,%5,%6,%7}, {%8,%9}, {%0,%1,%2,%3};"
                            : "+f"(c[mt][nt][0]), "+f"(c[mt][nt][1]),
                              "+f"(c[mt][nt][2]), "+f"(c[mt][nt][3])
                            : "r"(a[mt][0]), "r"(a[mt][1]), "r"(a[mt][2]), "r"(a[mt][3]),
                              "r"(b[nt][0]), "r"(b[nt][1]));
            }

            // ---- pos / exc extraction ----
            if (diag) {
                #pragma unroll
                for (int mt = 0; mt < 2; mt++)
                    #pragma unroll
                    for (int nt = 0; nt < 8; nt++)
                        #pragma unroll
                        for (int q = 0; q < 4; q++) {
                            int r_loc = wm + mt * 16 + (lane >> 2) + ((q & 2) << 2);
                            int c_loc = wn + nt * 8 + ((lane & 3) << 1) + (q & 1);
                            if (r_loc == c_loc)
                                g_pos[m0 + r_loc] = 2.0f * c[mt][nt][q];
                        }
            } else if (ni - mi == (HALF >> 7)) {
                #pragma unroll
                for (int mt = 0; mt < 2; mt++)
                    #pragma unroll
                    for (int nt = 0; nt < 8; nt++)
                        #pragma unroll
                        for (int q = 0; q < 4; q++) {
                            int r_loc = wm + mt * 16 + (lane >> 2) + ((q & 2) << 2);
                            int c_loc = wn + nt * 8 + ((lane & 3) << 1) + (q & 1);
                            if (r_loc == c_loc) {
                                float v = 2.0f * c[mt][nt][q];
                                g_exc[m0 + r_loc] = v;
                                g_exc[n0 + r_loc] = v;
                            }
                        }
            }

            // ---- epilogue ----
            float cs0[8], cs1[8];
            #pragma unroll
            for (int nt = 0; nt < 8; nt++) { cs0[nt] = 0.0f; cs1[nt] = 0.0f; }

            #pragma unroll
            for (int mt = 0; mt < 2; mt++) {
                float s0 = 0.0f, s1 = 0.0f;
                #pragma unroll
                for (int nt = 0; nt < 8; nt++) {
                    float e0 = ex2_approx(c[mt][nt][0] * TWO_LOG2E);
                    float e1 = ex2_approx(c[mt][nt][1] * TWO_LOG2E);
                    float e2 = ex2_approx(c[mt][nt][2] * TWO_LOG2E);
                    float e3 = ex2_approx(c[mt][nt][3] * TWO_LOG2E);
                    s0 += e0 + e1;
                    s1 += e2 + e3;
                    cs0[nt] += e0 + e2;
                    cs1[nt] += e1 + e3;
                }
                s0 += __shfl_xor_sync(0xFFFFFFFFu, s0, 1);
                s0 += __shfl_xor_sync(0xFFFFFFFFu, s0, 2);
                s1 += __shfl_xor_sync(0xFFFFFFFFu, s1, 1);
                s1 += __shfl_xor_sync(0xFFFFFFFFu, s1, 2);
                if ((lane & 3) == 0) {
                    int r = m0 + wm + mt * 16 + (lane >> 2);
                    atomicAdd(&g_rowsum[r],     s0);
                    atomicAdd(&g_rowsum[r + 8], s1);
                }
            }

            if (!diag) {
                #pragma unroll
                for (int nt = 0; nt < 8; nt++) {
                    float u = cs0[nt], v = cs1[nt];
                    u += __shfl_xor_sync(0xFFFFFFFFu, u, 4);
                    u += __shfl_xor_sync(0xFFFFFFFFu, u, 8);
                    u += __shfl_xor_sync(0xFFFFFFFFu, u, 16);
                    v += __shfl_xor_sync(0xFFFFFFFFu, v, 4);
                    v += __shfl_xor_sync(0xFFFFFFFFu, v, 8);
                    v += __shfl_xor_sync(0xFFFFFFFFu, v, 16);
                    if (lane < 4) {
                        int cix = n0 + wn + nt * 8 + (lane << 1);
                        atomicAdd(&g_rowsum[cix],     u);
                        atomicAdd(&g_rowsum[cix + 1], v);
                    }
                }
            }

            if (!last) {
                if (pf) {
                    CP_WAIT0();
                    __syncthreads();
                    cur ^= 1;
                } else {
                    __syncthreads();
                    load_tile_async(sb + SMEM_A, mi_n << 7, tid);
                    load_tile_async(sb + SMEM_B0 + (cur << 15), ni_n << 7, tid);
                    CP_COMMIT();
                    CP_WAIT0();
                    __syncthreads();
                }
                mi = mi_n; ni = ni_n;
            }
        }
    }
    grid_barrier(&g_bar1, &g_rel1);

    // ======================= phase 2: finalize ==============================
    {
        __shared__ float red[256];
        int r = bid * 256 + tid;
        float acc = 0.0f;
        if (r < N_TOTAL) {
            float S = g_rowsum[r] - ex2_approx(g_exc[r] * LOG2E);
            acc = logf(S) - g_pos[r];
        }
        red[tid] = acc;
        __syncthreads();
        #pragma unroll
        for (int s = 128; s > 0; s >>= 1) {
            if (tid < s) red[tid] += red[tid + s];
            __syncthreads();
        }
        if (tid == 0) {
            if (bid < N_TOTAL / 256) atomicAdd(&g_acc, red[0]);
            __threadfence();
            unsigned done = atomicAdd(&g_cnt, 1u);
            if (done == GRID_GRAM - 1) {
                float total = atomicAdd(&g_acc, 0.0f);
                out[0] = total / (float)N_TOTAL;
                // reset all persistent state for the next (graph-replayed) run
                g_acc = 0.0f;
                g_cnt = 0u;
                g_bar0 = 0u; g_rel0 = 0u;
                g_bar1 = 0u; g_rel1 = 0u;
                __threadfence();
            }
        }
    }
}

// ============================================================================
// launch
// ============================================================================
extern "C" void kernel_launch(void* const* d_in, const int* in_sizes, int n_in,
                              void* d_out, int out_size) {
    (void)in_sizes; (void)n_in; (void)out_size;
    const float* zi = (const float*)d_in[0];
    const float* zj = (const float*)d_in[1];
    float* out = (float*)d_out;

    cudaFuncSetAttribute(fused_kernel,
                         cudaFuncAttributeMaxDynamicSharedMemorySize, SMEM_TOT);
    fused_kernel<<<GRID_GRAM, 256, SMEM_TOT>>>(zi, zj, out);
}

// round 6
// speedup vs baseline: 1.0059x; 1.0059x over previous
#include <cuda_runtime.h>
#include <cuda_bf16.h>
#include <cstdint>

// ============================================================================
// NT-Xent loss, GB300 (sm_103a) -- HMMA symmetric-Gram, persistent CTAs.
// R6: A fragments register-resident across each tile row (reloaded only on
// mi change); inner loop processes tile in two 128x32 n-halves to fit regs.
// ============================================================================

#define N_TOTAL 8192
#define HALF    4096
#define DIM     128
#define TWO_LOG2E 2.8853900817779268f
#define LOG2E     1.4426950408889634f

#define GRID_GRAM 296

__device__ __nv_bfloat16 g_znb[N_TOTAL * DIM];
__device__ float g_rowsum[N_TOTAL];
__device__ float g_pos[N_TOTAL];
__device__ float g_exc[N_TOTAL];
__device__ float g_acc;
__device__ unsigned int g_cnt;

__device__ __forceinline__ uint32_t smem_to_u32(const void* p) {
    uint32_t a;
    asm("{ .reg .u64 t; cvta.to.shared.u64 t, %1; cvt.u32.u64 %0, t; }"
        : "=r"(a) : "l"(p));
    return a;
}
__device__ __forceinline__ float ex2_approx(float x) {
    float y;
    asm("ex2.approx.f32 %0, %1;" : "=f"(y) : "f"(x));
    return y;
}

// ============================================================================
// Kernel 1: normalize rows -> bf16, 2 rows per warp (front-batched loads)
// ============================================================================
__global__ void normalize_kernel(const float* __restrict__ zi,
                                 const float* __restrict__ zj) {
    int gw   = blockIdx.x * 8 + (threadIdx.x >> 5);   // 0..4095
    int lane = threadIdx.x & 31;
    int r0 = gw * 2, r1 = gw * 2 + 1;
    const float* s0 = (r0 < HALF) ? (zi + (size_t)r0 * DIM)
                                  : (zj + (size_t)(r0 - HALF) * DIM);
    const float* s1 = (r1 < HALF) ? (zi + (size_t)r1 * DIM)
                                  : (zj + (size_t)(r1 - HALF) * DIM);
    float4 v0 = reinterpret_cast<const float4*>(s0)[lane];
    float4 v1 = reinterpret_cast<const float4*>(s1)[lane];
    float a = v0.x * v0.x + v0.y * v0.y + v0.z * v0.z + v0.w * v0.w;
    float b = v1.x * v1.x + v1.y * v1.y + v1.z * v1.z + v1.w * v1.w;
    #pragma unroll
    for (int o = 16; o; o >>= 1) {
        a += __shfl_xor_sync(0xFFFFFFFFu, a, o);
        b += __shfl_xor_sync(0xFFFFFFFFu, b, o);
    }
    float ia = 1.0f / fmaxf(sqrtf(a), 1e-8f);
    float ib = 1.0f / fmaxf(sqrtf(b), 1e-8f);
    __nv_bfloat162* d0 =
        reinterpret_cast<__nv_bfloat162*>(g_znb + (size_t)r0 * DIM + lane * 4);
    __nv_bfloat162* d1 =
        reinterpret_cast<__nv_bfloat162*>(g_znb + (size_t)r1 * DIM + lane * 4);
    d0[0] = __floats2bfloat162_rn(v0.x * ia, v0.y * ia);
    d0[1] = __floats2bfloat162_rn(v0.z * ia, v0.w * ia);
    d1[0] = __floats2bfloat162_rn(v1.x * ib, v1.y * ib);
    d1[1] = __floats2bfloat162_rn(v1.z * ib, v1.w * ib);
    if (lane == 0) { g_rowsum[r0] = 0.0f; g_rowsum[r1] = 0.0f; }
    if (gw == 0 && lane == 0) { g_acc = 0.0f; g_cnt = 0u; }
}

// ============================================================================
// Kernel 2: persistent symmetric Gram GEMM, A-in-registers per tile row
// smem: A 32KB | B0 32KB | B1 32KB
// ============================================================================
#define SMEM_A   0
#define SMEM_B0  32768
#define SMEM_TOT 98304

__device__ __forceinline__ uint32_t tile_off(int row, int chunk16) {
    return (uint32_t)(row * 256 + ((chunk16 ^ (row & 7)) << 4));
}

__device__ __forceinline__ void load_tile_async(uint32_t sdst, int row0, int tid) {
    const uint4* gp = reinterpret_cast<const uint4*>(g_znb + (size_t)row0 * DIM);
    #pragma unroll
    for (int it = 0; it < 8; it++) {
        int idx = tid + it * 256;
        int row = idx >> 4, ch = idx & 15;
        asm volatile("cp.async.cg.shared.global [%0], [%1], 16;"
            :: "r"(sdst + tile_off(row, ch)), "l"(gp + (row << 4) + ch));
    }
}
#define CP_COMMIT() asm volatile("cp.async.commit_group;" ::: "memory")
#define CP_WAIT0()  asm volatile("cp.async.wait_group 0;"  ::: "memory")

__global__ void __launch_bounds__(256, 2)
gram_kernel() {
    extern __shared__ char smem[];
    uint32_t sb = smem_to_u32(smem);
    const int tid  = threadIdx.x;
    const int wid  = tid >> 5;
    const int lane = tid & 31;
    const int bid  = blockIdx.x;

    const int start = bid * 7 + (bid < 8 ? bid : 8);
    const int count = (bid < 8) ? 8 : 7;

    int mi = 0, rem = start, len = 64;
    while (rem >= len) { rem -= len; len--; mi++; }
    int ni = mi + rem;

    const int wm = (wid & 3) * 32;     // 4 m-strips of 32
    const int wn = (wid >> 2) * 64;    // 2 n-strips of 64
    const int l7 = lane & 7;
    const int g  = lane >> 3;

    load_tile_async(sb + SMEM_A, mi << 7, tid);
    load_tile_async(sb + SMEM_B0, ni << 7, tid);
    CP_COMMIT();
    CP_WAIT0();
    __syncthreads();
    int cur = 0;
    bool need_a = true;

    // A fragments: [mt][ks][4] -- register resident across the tile row
    uint32_t afr[2][8][4];

    for (int i = 0; i < count; i++) {
        const int m0 = mi << 7, n0 = ni << 7;
        const bool diag = (mi == ni);
        const bool last = (i == count - 1);
        int mi_n = mi, ni_n = ni + 1;
        if (ni_n == 64) { mi_n = mi + 1; ni_n = mi_n; }
        const bool pf = !last && (mi_n == mi);
        if (pf) {
            load_tile_async(sb + SMEM_B0 + ((1 - cur) << 15), ni_n << 7, tid);
            CP_COMMIT();
        }
        const uint32_t bbase = sb + SMEM_B0 + (cur << 15);

        if (need_a) {
            #pragma unroll
            for (int mt = 0; mt < 2; mt++) {
                int row = wm + mt * 16 + l7 + ((g & 1) << 3);
                #pragma unroll
                for (int ks = 0; ks < 8; ks++) {
                    uint32_t addr = sb + SMEM_A + tile_off(row, ks * 2 + (g >> 1));
                    asm volatile(
                        "ldmatrix.sync.aligned.m8n8.x4.shared.b16 {%0,%1,%2,%3}, [%4];"
                        : "=r"(afr[mt][ks][0]), "=r"(afr[mt][ks][1]),
                          "=r"(afr[mt][ks][2]), "=r"(afr[mt][ks][3])
                        : "r"(addr));
                }
            }
            need_a = false;
        }

        float rs0[2] = {0.0f, 0.0f}, rs1[2] = {0.0f, 0.0f};

        #pragma unroll
        for (int h = 0; h < 2; h++) {
            const int nbase = wn + h * 32;

            float c[2][4][4];
            #pragma unroll
            for (int mt = 0; mt < 2; mt++)
                #pragma unroll
                for (int nt = 0; nt < 4; nt++)
                    #pragma unroll
                    for (int q = 0; q < 4; q++) c[mt][nt][q] = 0.0f;

            #pragma unroll
            for (int ks = 0; ks < 8; ks++) {
                uint32_t b[4][2];
                #pragma unroll
                for (int nt2 = 0; nt2 < 2; nt2++) {
                    int row = nbase + nt2 * 16 + l7 + ((g >> 1) << 3);
                    uint32_t addr = bbase + tile_off(row, ks * 2 + (g & 1));
                    asm volatile(
                        "ldmatrix.sync.aligned.m8n8.x4.shared.b16 {%0,%1,%2,%3}, [%4];"
                        : "=r"(b[nt2 * 2][0]),     "=r"(b[nt2 * 2][1]),
                          "=r"(b[nt2 * 2 + 1][0]), "=r"(b[nt2 * 2 + 1][1])
                        : "r"(addr));
                }
                #pragma unroll
                for (int mt = 0; mt < 2; mt++)
                    #pragma unroll
                    for (int nt = 0; nt < 4; nt++)
                        asm volatile(
                            "mma.sync.aligned.m16n8k16.row.col.f32.bf16.bf16.f32 "
                            "{%0,%1,%2,%3}, {%4,%5,%6,%7}, {%8,%9}, {%0,%1,%2,%3};"
                            : "+f"(c[mt][nt][0]), "+f"(c[mt][nt][1]),
                              "+f"(c[mt][nt][2]), "+f"(c[mt][nt][3])
                            : "r"(afr[mt][ks][0]), "r"(afr[mt][ks][1]),
                              "r"(afr[mt][ks][2]), "r"(afr[mt][ks][3]),
                              "r"(b[nt][0]), "r"(b[nt][1]));
            }

            // ---- pos / exc extraction ----
            if (diag) {
                #pragma unroll
                for (int mt = 0; mt < 2; mt++)
                    #pragma unroll
                    for (int nt = 0; nt < 4; nt++)
                        #pragma unroll
                        for (int q = 0; q < 4; q++) {
                            int r_loc = wm + mt * 16 + (lane >> 2) + ((q & 2) << 2);
                            int c_loc = nbase + nt * 8 + ((lane & 3) << 1) + (q & 1);
                            if (r_loc == c_loc)
                                g_pos[m0 + r_loc] = 2.0f * c[mt][nt][q];
                        }
            } else if (ni - mi == (HALF >> 7)) {
                #pragma unroll
                for (int mt = 0; mt < 2; mt++)
                    #pragma unroll
                    for (int nt = 0; nt < 4; nt++)
                        #pragma unroll
                        for (int q = 0; q < 4; q++) {
                            int r_loc = wm + mt * 16 + (lane >> 2) + ((q & 2) << 2);
                            int c_loc = nbase + nt * 8 + ((lane & 3) << 1) + (q & 1);
                            if (r_loc == c_loc) {
                                float v = 2.0f * c[mt][nt][q];
                                g_exc[m0 + r_loc] = v;
                                g_exc[n0 + r_loc] = v;
                            }
                        }
            }

            // ---- exps: row partials (regs, across halves) + col sums ----
            float cs0[4], cs1[4];
            #pragma unroll
            for (int nt = 0; nt < 4; nt++) { cs0[nt] = 0.0f; cs1[nt] = 0.0f; }

            #pragma unroll
            for (int mt = 0; mt < 2; mt++) {
                #pragma unroll
                for (int nt = 0; nt < 4; nt++) {
                    float e0 = ex2_approx(c[mt][nt][0] * TWO_LOG2E);
                    float e1 = ex2_approx(c[mt][nt][1] * TWO_LOG2E);
                    float e2 = ex2_approx(c[mt][nt][2] * TWO_LOG2E);
                    float e3 = ex2_approx(c[mt][nt][3] * TWO_LOG2E);
                    rs0[mt] += e0 + e1;
                    rs1[mt] += e2 + e3;
                    cs0[nt] += e0 + e2;
                    cs1[nt] += e1 + e3;
                }
            }

            if (!diag) {
                #pragma unroll
                for (int nt = 0; nt < 4; nt++) {
                    float u = cs0[nt], v = cs1[nt];
                    u += __shfl_xor_sync(0xFFFFFFFFu, u, 4);
                    u += __shfl_xor_sync(0xFFFFFFFFu, u, 8);
                    u += __shfl_xor_sync(0xFFFFFFFFu, u, 16);
                    v += __shfl_xor_sync(0xFFFFFFFFu, v, 4);
                    v += __shfl_xor_sync(0xFFFFFFFFu, v, 8);
                    v += __shfl_xor_sync(0xFFFFFFFFu, v, 16);
                    if (lane < 4) {
                        int cix = n0 + nbase + nt * 8 + (lane << 1);
                        atomicAdd(&g_rowsum[cix],     u);
                        atomicAdd(&g_rowsum[cix + 1], v);
                    }
                }
            }
        }

        // ---- row sums: one shuffle+atomic pass per tile ----
        #pragma unroll
        for (int mt = 0; mt < 2; mt++) {
            float s0 = rs0[mt], s1 = rs1[mt];
            s0 += __shfl_xor_sync(0xFFFFFFFFu, s0, 1);
            s0 += __shfl_xor_sync(0xFFFFFFFFu, s0, 2);
            s1 += __shfl_xor_sync(0xFFFFFFFFu, s1, 1);
            s1 += __shfl_xor_sync(0xFFFFFFFFu, s1, 2);
            if ((lane & 3) == 0) {
                int r = m0 + wm + mt * 16 + (lane >> 2);
                atomicAdd(&g_rowsum[r],     s0);
                atomicAdd(&g_rowsum[r + 8], s1);
            }
        }

        // ---- advance pipeline ----
        if (!last) {
            if (pf) {
                CP_WAIT0();
                __syncthreads();
                cur ^= 1;
            } else {
                __syncthreads();
                load_tile_async(sb + SMEM_A, mi_n << 7, tid);
                load_tile_async(sb + SMEM_B0 + (cur << 15), ni_n << 7, tid);
                CP_COMMIT();
                CP_WAIT0();
                __syncthreads();
                need_a = true;
            }
            mi = mi_n; ni = ni_n;
        }
    }
}

// ============================================================================
// Kernel 3: finalize -> scalar loss (32 CTAs, last block writes)
// ============================================================================
__global__ void finalize_kernel(float* __restrict__ out) {
    __shared__ float red[256];
    int r = blockIdx.x * 256 + threadIdx.x;
    float S = g_rowsum[r] - ex2_approx(g_exc[r] * LOG2E);
    float acc = logf(S) - g_pos[r];
    red[threadIdx.x] = acc;
    __syncthreads();
    #pragma unroll
    for (int s = 128; s > 0; s >>= 1) {
        if (threadIdx.x < s) red[threadIdx.x] += red[threadIdx.x + s];
        __syncthreads();
    }
    if (threadIdx.x == 0) {
        atomicAdd(&g_acc, red[0]);
        __threadfence();
        unsigned done = atomicAdd(&g_cnt, 1u);
        if (done == gridDim.x - 1) {
            float total = atomicAdd(&g_acc, 0.0f);
            out[0] = total / (float)N_TOTAL;
        }
    }
}

// ============================================================================
// launch
// ============================================================================
extern "C" void kernel_launch(void* const* d_in, const int* in_sizes, int n_in,
                              void* d_out, int out_size) {
    (void)in_sizes; (void)n_in; (void)out_size;
    const float* zi = (const float*)d_in[0];
    const float* zj = (const float*)d_in[1];
    float* out = (float*)d_out;

    normalize_kernel<<<N_TOTAL / 16, 256>>>(zi, zj);

    cudaFuncSetAttribute(gram_kernel,
                         cudaFuncAttributeMaxDynamicSharedMemorySize, SMEM_TOT);
    gram_kernel<<<GRID_GRAM, 256, SMEM_TOT>>>();

    finalize_kernel<<<N_TOTAL / 256, 256>>>(out);
}

// round 7
// speedup vs baseline: 1.0556x; 1.0494x over previous
#include <cuda_runtime.h>
#include <cuda_bf16.h>
#include <cstdint>

// ============================================================================
// NT-Xent loss, GB300 (sm_103a) -- HMMA symmetric-Gram, persistent CTAs,
// R7: 512-thread gram CTAs (warp tile 32x32, 32 warps/SM) + sqrt(2log2e)
// prescale so epilogue is a bare ex2 per element.
// ============================================================================

#define N_TOTAL 8192
#define HALF    4096
#define DIM     128
#define LOG2E      1.4426950408889634f
#define INV_LOG2E  0.6931471805599453f
#define SQRT_T     1.6986435838080746f   // sqrt(2*log2(e))

#define GRID_GRAM 296

__device__ __nv_bfloat16 g_znb[N_TOTAL * DIM];   // rows scaled by SQRT_T
__device__ float g_rowsum[N_TOTAL];
__device__ float g_pos[N_TOTAL];                 // stores 2log2e * dot
__device__ float g_exc[N_TOTAL];                 // stores 2log2e * dot
__device__ float g_acc;
__device__ unsigned int g_cnt;

__device__ __forceinline__ uint32_t smem_to_u32(const void* p) {
    uint32_t a;
    asm("{ .reg .u64 t; cvta.to.shared.u64 t, %1; cvt.u32.u64 %0, t; }"
        : "=r"(a) : "l"(p));
    return a;
}
__device__ __forceinline__ float ex2_approx(float x) {
    float y;
    asm("ex2.approx.f32 %0, %1;" : "=f"(y) : "f"(x));
    return y;
}

// ============================================================================
// Kernel 1: normalize rows -> bf16 scaled by SQRT_T (one warp per row)
// ============================================================================
__global__ void normalize_kernel(const float* __restrict__ zi,
                                 const float* __restrict__ zj) {
    int row  = blockIdx.x * 8 + (threadIdx.x >> 5);
    int lane = threadIdx.x & 31;
    const float* src = (row < HALF) ? (zi + (size_t)row * DIM)
                                    : (zj + (size_t)(row - HALF) * DIM);
    float4 v = reinterpret_cast<const float4*>(src)[lane];
    float ss = v.x * v.x + v.y * v.y + v.z * v.z + v.w * v.w;
    #pragma unroll
    for (int o = 16; o; o >>= 1) ss += __shfl_xor_sync(0xFFFFFFFFu, ss, o);
    float inv = SQRT_T / fmaxf(sqrtf(ss), 1e-8f);
    __nv_bfloat162* dst =
        reinterpret_cast<__nv_bfloat162*>(g_znb + (size_t)row * DIM + lane * 4);
    dst[0] = __floats2bfloat162_rn(v.x * inv, v.y * inv);
    dst[1] = __floats2bfloat162_rn(v.z * inv, v.w * inv);
    if (lane == 0) g_rowsum[row] = 0.0f;
    if (row == 0 && lane == 0) { g_acc = 0.0f; g_cnt = 0u; }
}

// ============================================================================
// Kernel 2: persistent symmetric Gram GEMM, 512 threads, warp tile 32x32
// smem: A 32KB | B0 32KB | B1 32KB
// ============================================================================
#define SMEM_A   0
#define SMEM_B0  32768
#define SMEM_TOT 98304

__device__ __forceinline__ uint32_t tile_off(int row, int chunk16) {
    return (uint32_t)(row * 256 + ((chunk16 ^ (row & 7)) << 4));
}

__device__ __forceinline__ void load_tile_async(uint32_t sdst, int row0, int tid) {
    const uint4* gp = reinterpret_cast<const uint4*>(g_znb + (size_t)row0 * DIM);
    #pragma unroll
    for (int it = 0; it < 4; it++) {
        int idx = tid + it * 512;
        int row = idx >> 4, ch = idx & 15;
        asm volatile("cp.async.cg.shared.global [%0], [%1], 16;"
            :: "r"(sdst + tile_off(row, ch)), "l"(gp + (row << 4) + ch));
    }
}
#define CP_COMMIT() asm volatile("cp.async.commit_group;" ::: "memory")
#define CP_WAIT0()  asm volatile("cp.async.wait_group 0;"  ::: "memory")

__global__ void __launch_bounds__(512, 2)
gram_kernel() {
    extern __shared__ char smem[];
    uint32_t sb = smem_to_u32(smem);
    const int tid  = threadIdx.x;
    const int wid  = tid >> 5;           // 0..15
    const int lane = tid & 31;
    const int bid  = blockIdx.x;

    const int start = bid * 7 + (bid < 8 ? bid : 8);
    const int count = (bid < 8) ? 8 : 7;

    int mi = 0, rem = start, len = 64;
    while (rem >= len) { rem -= len; len--; mi++; }
    int ni = mi + rem;

    const int wm = (wid & 3) * 32;       // 4 m-strips of 32
    const int wn = (wid >> 2) * 32;      // 4 n-strips of 32
    const int l7 = lane & 7;
    const int g  = lane >> 3;

    load_tile_async(sb + SMEM_A, mi << 7, tid);
    load_tile_async(sb + SMEM_B0, ni << 7, tid);
    CP_COMMIT();
    CP_WAIT0();
    __syncthreads();
    int cur = 0;

    for (int i = 0; i < count; i++) {
        const int m0 = mi << 7, n0 = ni << 7;
        const bool diag = (mi == ni);
        const bool last = (i == count - 1);
        int mi_n = mi, ni_n = ni + 1;
        if (ni_n == 64) { mi_n = mi + 1; ni_n = mi_n; }
        const bool pf = !last && (mi_n == mi);
        if (pf) {
            load_tile_async(sb + SMEM_B0 + ((1 - cur) << 15), ni_n << 7, tid);
            CP_COMMIT();
        }
        const uint32_t bbase = sb + SMEM_B0 + (cur << 15);

        // ---- MMA mainloop: warp tile 32x32 ----
        float c[2][4][4];
        #pragma unroll
        for (int mt = 0; mt < 2; mt++)
            #pragma unroll
            for (int nt = 0; nt < 4; nt++)
                #pragma unroll
                for (int q = 0; q < 4; q++) c[mt][nt][q] = 0.0f;

        #pragma unroll
        for (int ks = 0; ks < 8; ks++) {
            uint32_t a[2][4];
            #pragma unroll
            for (int mt = 0; mt < 2; mt++) {
                int row = wm + mt * 16 + l7 + ((g & 1) << 3);
                uint32_t addr = sb + SMEM_A + tile_off(row, ks * 2 + (g >> 1));
                asm volatile(
                    "ldmatrix.sync.aligned.m8n8.x4.shared.b16 {%0,%1,%2,%3}, [%4];"
                    : "=r"(a[mt][0]), "=r"(a[mt][1]), "=r"(a[mt][2]), "=r"(a[mt][3])
                    : "r"(addr));
            }
            uint32_t b[4][2];
            #pragma unroll
            for (int nt2 = 0; nt2 < 2; nt2++) {
                int row = wn + nt2 * 16 + l7 + ((g >> 1) << 3);
                uint32_t addr = bbase + tile_off(row, ks * 2 + (g & 1));
                asm volatile(
                    "ldmatrix.sync.aligned.m8n8.x4.shared.b16 {%0,%1,%2,%3}, [%4];"
                    : "=r"(b[nt2 * 2][0]),     "=r"(b[nt2 * 2][1]),
                      "=r"(b[nt2 * 2 + 1][0]), "=r"(b[nt2 * 2 + 1][1])
                    : "r"(addr));
            }
            #pragma unroll
            for (int mt = 0; mt < 2; mt++)
                #pragma unroll
                for (int nt = 0; nt < 4; nt++)
                    asm volatile(
                        "mma.sync.aligned.m16n8k16.row.col.f32.bf16.bf16.f32 "
                        "{%0,%1,%2,%3}, {%4,%5,%6,%7}, {%8,%9}, {%0,%1,%2,%3};"
                        : "+f"(c[mt][nt][0]), "+f"(c[mt][nt][1]),
                          "+f"(c[mt][nt][2]), "+f"(c[mt][nt][3])
                        : "r"(a[mt][0]), "r"(a[mt][1]), "r"(a[mt][2]), "r"(a[mt][3]),
                          "r"(b[nt][0]), "r"(b[nt][1]));
        }

        // ---- pos / exc extraction (values in 2log2e*dot units) ----
        if (diag) {
            #pragma unroll
            for (int mt = 0; mt < 2; mt++)
                #pragma unroll
                for (int nt = 0; nt < 4; nt++)
                    #pragma unroll
                    for (int q = 0; q < 4; q++) {
                        int r_loc = wm + mt * 16 + (lane >> 2) + ((q & 2) << 2);
                        int c_loc = wn + nt * 8 + ((lane & 3) << 1) + (q & 1);
                        if (r_loc == c_loc)
                            g_pos[m0 + r_loc] = c[mt][nt][q];
                    }
        } else if (ni - mi == (HALF >> 7)) {
            #pragma unroll
            for (int mt = 0; mt < 2; mt++)
                #pragma unroll
                for (int nt = 0; nt < 4; nt++)
                    #pragma unroll
                    for (int q = 0; q < 4; q++) {
                        int r_loc = wm + mt * 16 + (lane >> 2) + ((q & 2) << 2);
                        int c_loc = wn + nt * 8 + ((lane & 3) << 1) + (q & 1);
                        if (r_loc == c_loc) {
                            float v = c[mt][nt][q];
                            g_exc[m0 + r_loc] = v;
                            g_exc[n0 + r_loc] = v;
                        }
                    }
        }

        // ---- epilogue: bare ex2; row sums + col sums ----
        float cs0[4], cs1[4];
        #pragma unroll
        for (int nt = 0; nt < 4; nt++) { cs0[nt] = 0.0f; cs1[nt] = 0.0f; }

        #pragma unroll
        for (int mt = 0; mt < 2; mt++) {
            float s0 = 0.0f, s1 = 0.0f;
            #pragma unroll
            for (int nt = 0; nt < 4; nt++) {
                float e0 = ex2_approx(c[mt][nt][0]);
                float e1 = ex2_approx(c[mt][nt][1]);
                float e2 = ex2_approx(c[mt][nt][2]);
                float e3 = ex2_approx(c[mt][nt][3]);
                s0 += e0 + e1;
                s1 += e2 + e3;
                cs0[nt] += e0 + e2;
                cs1[nt] += e1 + e3;
            }
            s0 += __shfl_xor_sync(0xFFFFFFFFu, s0, 1);
            s0 += __shfl_xor_sync(0xFFFFFFFFu, s0, 2);
            s1 += __shfl_xor_sync(0xFFFFFFFFu, s1, 1);
            s1 += __shfl_xor_sync(0xFFFFFFFFu, s1, 2);
            if ((lane & 3) == 0) {
                int r = m0 + wm + mt * 16 + (lane >> 2);
                atomicAdd(&g_rowsum[r],     s0);
                atomicAdd(&g_rowsum[r + 8], s1);
            }
        }

        if (!diag) {
            #pragma unroll
            for (int nt = 0; nt < 4; nt++) {
                float u = cs0[nt], v = cs1[nt];
                u += __shfl_xor_sync(0xFFFFFFFFu, u, 4);
                u += __shfl_xor_sync(0xFFFFFFFFu, u, 8);
                u += __shfl_xor_sync(0xFFFFFFFFu, u, 16);
                v += __shfl_xor_sync(0xFFFFFFFFu, v, 4);
                v += __shfl_xor_sync(0xFFFFFFFFu, v, 8);
                v += __shfl_xor_sync(0xFFFFFFFFu, v, 16);
                if (lane < 4) {
                    int cix = n0 + wn + nt * 8 + (lane << 1);
                    atomicAdd(&g_rowsum[cix],     u);
                    atomicAdd(&g_rowsum[cix + 1], v);
                }
            }
        }

        // ---- advance pipeline ----
        if (!last) {
            if (pf) {
                CP_WAIT0();
                __syncthreads();
                cur ^= 1;
            } else {
                __syncthreads();
                load_tile_async(sb + SMEM_A, mi_n << 7, tid);
                load_tile_async(sb + SMEM_B0 + (cur << 15), ni_n << 7, tid);
                CP_COMMIT();
                CP_WAIT0();
                __syncthreads();
            }
            mi = mi_n; ni = ni_n;
        }
    }
}

// ============================================================================
// Kernel 3: finalize -> scalar loss
// g_exc/g_pos are in 2log2e*dot units: exp = ex2(exc), pos = pos/log2e
// ============================================================================
__global__ void finalize_kernel(float* __restrict__ out) {
    __shared__ float red[256];
    int r = blockIdx.x * 256 + threadIdx.x;
    float S = g_rowsum[r] - ex2_approx(g_exc[r]);
    float acc = logf(S) - g_pos[r] * INV_LOG2E;
    red[threadIdx.x] = acc;
    __syncthreads();
    #pragma unroll
    for (int s = 128; s > 0; s >>= 1) {
        if (threadIdx.x < s) red[threadIdx.x] += red[threadIdx.x + s];
        __syncthreads();
    }
    if (threadIdx.x == 0) {
        atomicAdd(&g_acc, red[0]);
        __threadfence();
        unsigned done = atomicAdd(&g_cnt, 1u);
        if (done == gridDim.x - 1) {
            float total = atomicAdd(&g_acc, 0.0f);
            out[0] = total / (float)N_TOTAL;
        }
    }
}

// ============================================================================
// launch
// ============================================================================
extern "C" void kernel_launch(void* const* d_in, const int* in_sizes, int n_in,
                              void* d_out, int out_size) {
    (void)in_sizes; (void)n_in; (void)out_size;
    const float* zi = (const float*)d_in[0];
    const float* zj = (const float*)d_in[1];
    float* out = (float*)d_out;

    normalize_kernel<<<N_TOTAL / 8, 256>>>(zi, zj);

    cudaFuncSetAttribute(gram_kernel,
                         cudaFuncAttributeMaxDynamicSharedMemorySize, SMEM_TOT);
    gram_kernel<<<GRID_GRAM, 512, SMEM_TOT>>>();

    finalize_kernel<<<N_TOTAL / 256, 256>>>(out);
}